// round 3
// baseline (speedup 1.0000x reference)
#include <cuda_runtime.h>

// out[i] = sum_j relu(adj[i,j] * Linv[i,j]) * W[j] + b
// N = 8192. Inputs: d_in[0]=x_e (unused), d_in[1]=Linv, d_in[2]=adjacency,
// d_in[3]=W (N floats), d_in[4]=b (1 float). Output: N floats ([N,1]).

#define N_DIM 8192
#define THREADS 256
#define ROWS_PER_CTA 4

__global__ __launch_bounds__(THREADS)
void dist2cycle_rowdot4_kernel(const float4* __restrict__ Linv,
                               const float4* __restrict__ adj,
                               const float4* __restrict__ W4,
                               const float*  __restrict__ bptr,
                               float* __restrict__ out) {
    const int row0 = blockIdx.x * ROWS_PER_CTA;
    const size_t stride = N_DIM / 4;          // float4 per row
    const size_t base = (size_t)row0 * stride;

    const float4* __restrict__ L0 = Linv + base;
    const float4* __restrict__ A0 = adj  + base;

    float acc0 = 0.0f, acc1 = 0.0f, acc2 = 0.0f, acc3 = 0.0f;

    // 2048 float4 per row; 256 threads -> 8 iterations, 9 LDG.128 per iter.
    #pragma unroll 4
    for (int j = threadIdx.x; j < N_DIM / 4; j += THREADS) {
        float4 w  = __ldg(&W4[j]);
        float4 l0 = __ldcs(&L0[j]);
        float4 a0 = __ldcs(&A0[j]);
        float4 l1 = __ldcs(&L0[j + stride]);
        float4 a1 = __ldcs(&A0[j + stride]);
        float4 l2 = __ldcs(&L0[j + 2 * stride]);
        float4 a2 = __ldcs(&A0[j + 2 * stride]);
        float4 l3 = __ldcs(&L0[j + 3 * stride]);
        float4 a3 = __ldcs(&A0[j + 3 * stride]);

        acc0 = fmaf(fmaxf(a0.x * l0.x, 0.0f), w.x, acc0);
        acc0 = fmaf(fmaxf(a0.y * l0.y, 0.0f), w.y, acc0);
        acc0 = fmaf(fmaxf(a0.z * l0.z, 0.0f), w.z, acc0);
        acc0 = fmaf(fmaxf(a0.w * l0.w, 0.0f), w.w, acc0);

        acc1 = fmaf(fmaxf(a1.x * l1.x, 0.0f), w.x, acc1);
        acc1 = fmaf(fmaxf(a1.y * l1.y, 0.0f), w.y, acc1);
        acc1 = fmaf(fmaxf(a1.z * l1.z, 0.0f), w.z, acc1);
        acc1 = fmaf(fmaxf(a1.w * l1.w, 0.0f), w.w, acc1);

        acc2 = fmaf(fmaxf(a2.x * l2.x, 0.0f), w.x, acc2);
        acc2 = fmaf(fmaxf(a2.y * l2.y, 0.0f), w.y, acc2);
        acc2 = fmaf(fmaxf(a2.z * l2.z, 0.0f), w.z, acc2);
        acc2 = fmaf(fmaxf(a2.w * l2.w, 0.0f), w.w, acc2);

        acc3 = fmaf(fmaxf(a3.x * l3.x, 0.0f), w.x, acc3);
        acc3 = fmaf(fmaxf(a3.y * l3.y, 0.0f), w.y, acc3);
        acc3 = fmaf(fmaxf(a3.z * l3.z, 0.0f), w.z, acc3);
        acc3 = fmaf(fmaxf(a3.w * l3.w, 0.0f), w.w, acc3);
    }

    // Reduce 4 accumulators across the block.
    const int lane = threadIdx.x & 31;
    const int wid  = threadIdx.x >> 5;

    #pragma unroll
    for (int off = 16; off > 0; off >>= 1) {
        acc0 += __shfl_xor_sync(0xFFFFFFFFu, acc0, off);
        acc1 += __shfl_xor_sync(0xFFFFFFFFu, acc1, off);
        acc2 += __shfl_xor_sync(0xFFFFFFFFu, acc2, off);
        acc3 += __shfl_xor_sync(0xFFFFFFFFu, acc3, off);
    }

    __shared__ float warp_sums[4][THREADS / 32];
    if (lane == 0) {
        warp_sums[0][wid] = acc0;
        warp_sums[1][wid] = acc1;
        warp_sums[2][wid] = acc2;
        warp_sums[3][wid] = acc3;
    }
    __syncthreads();

    // First 4 warps each finish one row (8 partial sums per row).
    if (wid < ROWS_PER_CTA) {
        float v = (lane < THREADS / 32) ? warp_sums[wid][lane] : 0.0f;
        #pragma unroll
        for (int off = 4; off > 0; off >>= 1)
            v += __shfl_xor_sync(0xFFFFFFFFu, v, off);
        if (lane == 0)
            out[row0 + wid] = v + __ldg(bptr);
    }
}

extern "C" void kernel_launch(void* const* d_in, const int* in_sizes, int n_in,
                              void* d_out, int out_size) {
    // metadata order: x_e, Linv, adjacency, W, b
    const float4* Linv = (const float4*)d_in[1];
    const float4* adj  = (const float4*)d_in[2];
    const float4* W4   = (const float4*)d_in[3];
    const float*  b    = (const float*)d_in[4];
    float* out = (float*)d_out;

    dist2cycle_rowdot4_kernel<<<N_DIM / ROWS_PER_CTA, THREADS>>>(Linv, adj, W4, b, out);
}

// round 4
// speedup vs baseline: 1.0865x; 1.0865x over previous
#include <cuda_runtime.h>

// out[i] = sum_j relu(adj[i,j] * Linv[i,j]) * W[j] + b
// N = 8192. Inputs: d_in[0]=x_e (unused), d_in[1]=Linv, d_in[2]=adjacency,
// d_in[3]=W (N floats), d_in[4]=b (1 float). Output: N floats ([N,1]).

#define N_DIM 8192
#define THREADS 256
#define ITERS (N_DIM / 4 / THREADS)   // 8

__global__ __launch_bounds__(THREADS)
void dist2cycle_rowdot_pipe_kernel(const float4* __restrict__ Linv,
                                   const float4* __restrict__ adj,
                                   const float4* __restrict__ W4,
                                   const float*  __restrict__ bptr,
                                   float* __restrict__ out) {
    const int row = blockIdx.x;
    const size_t base = (size_t)row * (N_DIM / 4);
    const float4* __restrict__ L = Linv + base;
    const float4* __restrict__ A = adj  + base;

    float acc = 0.0f;

    // Software pipeline: always keep next iteration's 3 LDG.128 in flight
    // while reducing the current one.
    int j = threadIdx.x;
    float4 l_cur = __ldcs(&L[j]);
    float4 a_cur = __ldcs(&A[j]);
    float4 w_cur = __ldg(&W4[j]);

    #pragma unroll
    for (int it = 0; it < ITERS - 1; ++it) {
        const int jn = j + THREADS;
        float4 l_nxt = __ldcs(&L[jn]);
        float4 a_nxt = __ldcs(&A[jn]);
        float4 w_nxt = __ldg(&W4[jn]);

        acc = fmaf(fmaxf(a_cur.x * l_cur.x, 0.0f), w_cur.x, acc);
        acc = fmaf(fmaxf(a_cur.y * l_cur.y, 0.0f), w_cur.y, acc);
        acc = fmaf(fmaxf(a_cur.z * l_cur.z, 0.0f), w_cur.z, acc);
        acc = fmaf(fmaxf(a_cur.w * l_cur.w, 0.0f), w_cur.w, acc);

        l_cur = l_nxt;
        a_cur = a_nxt;
        w_cur = w_nxt;
        j = jn;
    }

    acc = fmaf(fmaxf(a_cur.x * l_cur.x, 0.0f), w_cur.x, acc);
    acc = fmaf(fmaxf(a_cur.y * l_cur.y, 0.0f), w_cur.y, acc);
    acc = fmaf(fmaxf(a_cur.z * l_cur.z, 0.0f), w_cur.z, acc);
    acc = fmaf(fmaxf(a_cur.w * l_cur.w, 0.0f), w_cur.w, acc);

    // Warp reduce
    #pragma unroll
    for (int off = 16; off > 0; off >>= 1)
        acc += __shfl_xor_sync(0xFFFFFFFFu, acc, off);

    // Block reduce across 8 warps
    __shared__ float warp_sums[THREADS / 32];
    const int lane = threadIdx.x & 31;
    const int wid  = threadIdx.x >> 5;
    if (lane == 0) warp_sums[wid] = acc;
    __syncthreads();

    if (wid == 0) {
        float v = (lane < THREADS / 32) ? warp_sums[lane] : 0.0f;
        #pragma unroll
        for (int off = 4; off > 0; off >>= 1)
            v += __shfl_xor_sync(0xFFFFFFFFu, v, off);
        if (lane == 0)
            out[row] = v + __ldg(bptr);
    }
}

extern "C" void kernel_launch(void* const* d_in, const int* in_sizes, int n_in,
                              void* d_out, int out_size) {
    // metadata order: x_e, Linv, adjacency, W, b
    const float4* Linv = (const float4*)d_in[1];
    const float4* adj  = (const float4*)d_in[2];
    const float4* W4   = (const float4*)d_in[3];
    const float*  b    = (const float*)d_in[4];
    float* out = (float*)d_out;

    dist2cycle_rowdot_pipe_kernel<<<N_DIM, THREADS>>>(Linv, adj, W4, b, out);
}

// round 8
// speedup vs baseline: 1.1087x; 1.0204x over previous
#include <cuda_runtime.h>

// out[i] = sum_j relu(adj[i,j] * Linv[i,j]) * W[j] + b
// N = 8192. Inputs: d_in[0]=x_e (unused), d_in[1]=Linv, d_in[2]=adjacency,
// d_in[3]=W (N floats), d_in[4]=b (1 float). Output: N floats ([N,1]).

#define N_DIM 8192
#define THREADS 256

__global__ __launch_bounds__(THREADS, 8)   // force <=32 regs -> 8 CTAs/SM -> 64 warps
void dist2cycle_rowdot_occ_kernel(const float4* __restrict__ Linv,
                                  const float4* __restrict__ adj,
                                  const float4* __restrict__ W4,
                                  const float*  __restrict__ bptr,
                                  float* __restrict__ out) {
    const int row = blockIdx.x;
    const size_t base = (size_t)row * (N_DIM / 4);
    const float4* __restrict__ L = Linv + base;
    const float4* __restrict__ A = adj  + base;

    float acc = 0.0f;

    // 2048 float4 per row; 256 threads -> 8 iterations.
    #pragma unroll 8
    for (int j = threadIdx.x; j < N_DIM / 4; j += THREADS) {
        float4 l = __ldcs(&L[j]);
        float4 a = __ldcs(&A[j]);
        float4 w = __ldg(&W4[j]);
        acc = fmaf(fmaxf(a.x * l.x, 0.0f), w.x, acc);
        acc = fmaf(fmaxf(a.y * l.y, 0.0f), w.y, acc);
        acc = fmaf(fmaxf(a.z * l.z, 0.0f), w.z, acc);
        acc = fmaf(fmaxf(a.w * l.w, 0.0f), w.w, acc);
    }

    // Warp reduce
    #pragma unroll
    for (int off = 16; off > 0; off >>= 1)
        acc += __shfl_xor_sync(0xFFFFFFFFu, acc, off);

    // Block reduce across 8 warps
    __shared__ float warp_sums[THREADS / 32];
    const int lane = threadIdx.x & 31;
    const int wid  = threadIdx.x >> 5;
    if (lane == 0) warp_sums[wid] = acc;
    __syncthreads();

    if (wid == 0) {
        float v = (lane < THREADS / 32) ? warp_sums[lane] : 0.0f;
        #pragma unroll
        for (int off = 4; off > 0; off >>= 1)
            v += __shfl_xor_sync(0xFFFFFFFFu, v, off);
        if (lane == 0)
            out[row] = v + __ldg(bptr);
    }
}

extern "C" void kernel_launch(void* const* d_in, const int* in_sizes, int n_in,
                              void* d_out, int out_size) {
    // metadata order: x_e, Linv, adjacency, W, b
    const float4* Linv = (const float4*)d_in[1];
    const float4* adj  = (const float4*)d_in[2];
    const float4* W4   = (const float4*)d_in[3];
    const float*  b    = (const float*)d_in[4];
    float* out = (float*)d_out;

    dist2cycle_rowdot_occ_kernel<<<N_DIM, THREADS>>>(Linv, adj, W4, b, out);
}